// round 13
// baseline (speedup 1.0000x reference)
#include <cuda_runtime.h>

#define BB 512
#define DD 512
#define NN 196
#define NP 224   // n padded to 7*32

// scratch (no cudaMalloc allowed)
__device__ float g_mem[BB * DD];
__device__ float g_v1[BB * DD];
__device__ float g_v2[BB * DD];

// ---------------------------------------------------------------------------
// Fused GEMM:  mem = ms @ Wm^T + bm          (f-tiles 0..7)
//              v   = (ctrl*Wattn) @ Wcat     (f-tiles 8..23 -> v1 | v2)
// 32(b) x 64(f) tile, 128 threads, 4x4 per thread, k-tile 16. grid 24x16=384.
// PLUS: fire-and-forget L2 prefetch of the attn kernel's consumption front
// (first 16 rows of each 64-row warp region, kb+kbp, all batches ~103 MB)
// issued up-front — fills the otherwise idle DRAM pipe during the GEMM stage.
// ---------------------------------------------------------------------------
__global__ __launch_bounds__(128) void gemm_kernel(
    const float* __restrict__ ms, const float* __restrict__ Wm,
    const float* __restrict__ bm, const float* __restrict__ ctrl,
    const float* __restrict__ Wattn, const float* __restrict__ Wcat,
    float* __restrict__ memo, float* __restrict__ v1, float* __restrict__ v2,
    const float* __restrict__ kb, const float* __restrict__ kbp)
{
    __shared__ float As[16][36];
    __shared__ float Bs[16][68];
    const int t = threadIdx.x;
    const int tx = t & 15, ty = t >> 4;
    const int b0 = blockIdx.y * 32;
    const bool is_mem = (blockIdx.x < 8);
    const int f0 = is_mem ? blockIdx.x * 64 : (blockIdx.x - 8) * 64;
    const int arow = t >> 2, kq = (t & 3) << 2;
    float acc[4][4] = {};

    // ---- L2 prefetch of attn consumption front (fire-and-forget) ----
    // items: arr(2) x b(512) x reg(8) x row(16) x line(7)  = 917504
    {
        const int gid = (blockIdx.y * 24 + blockIdx.x) * 128 + t;
        const int NTH = 384 * 128;                 // 49152 threads
        for (int i = gid; i < 917504; i += NTH) {
            const int arr = (i >= 458752);
            const int j = i - arr * 458752;
            const int line = j % 7;
            const int r2 = j / 7;                  // 0..65535
            const int row = r2 & 15;
            const int reg = (r2 >> 4) & 7;
            const int b   = r2 >> 7;               // 0..511
            const int d   = reg * 64 + row;
            const float* base = arr ? kbp : kb;
            const float* p = base + ((size_t)b * DD + d) * NN + line * 32;
            asm volatile("prefetch.global.L2 [%0];" :: "l"(p));
        }
    }

    for (int k0 = 0; k0 < DD; k0 += 16) {
        float4 av;
        if (is_mem) {
            av = *(const float4*)(ms + (b0 + arow) * DD + k0 + kq);
        } else {
            float4 c4 = *(const float4*)(ctrl + (b0 + arow) * DD + k0 + kq);
            float4 w4 = *(const float4*)(Wattn + k0 + kq);
            av = make_float4(c4.x * w4.x, c4.y * w4.y, c4.z * w4.z, c4.w * w4.w);
        }
        As[kq + 0][arow] = av.x; As[kq + 1][arow] = av.y;
        As[kq + 2][arow] = av.z; As[kq + 3][arow] = av.w;

        if (is_mem) {  // Wm[f][k] -> transpose to Bs[k][f]
#pragma unroll
            for (int r = 0; r < 2; r++) {
                int idx = t + 128 * r;
                int fr = idx >> 2, kk = (idx & 3) << 2;
                float4 bv = *(const float4*)(Wm + (f0 + fr) * DD + k0 + kk);
                Bs[kk + 0][fr] = bv.x; Bs[kk + 1][fr] = bv.y;
                Bs[kk + 2][fr] = bv.z; Bs[kk + 3][fr] = bv.w;
            }
        } else {       // Wcat[k][f] already k-major
#pragma unroll
            for (int r = 0; r < 2; r++) {
                int idx = t + 128 * r;
                int kk = idx >> 4, fq = (idx & 15) << 2;
                *(float4*)&Bs[kk][fq] =
                    *(const float4*)(Wcat + (size_t)(k0 + kk) * (2 * DD) + f0 + fq);
            }
        }
        __syncthreads();
#pragma unroll
        for (int k = 0; k < 16; k++) {
            float4 a = *(const float4*)&As[k][ty * 4];
            float4 b = *(const float4*)&Bs[k][tx * 4];
            float aa[4] = {a.x, a.y, a.z, a.w};
            float bb[4] = {b.x, b.y, b.z, b.w};
#pragma unroll
            for (int r = 0; r < 4; r++)
#pragma unroll
                for (int c = 0; c < 4; c++) acc[r][c] += aa[r] * bb[c];
        }
        __syncthreads();
    }

#pragma unroll
    for (int r = 0; r < 4; r++) {
        int b = b0 + ty * 4 + r;
#pragma unroll
        for (int c = 0; c < 4; c++) {
            int f = f0 + tx * 4 + c;
            if (is_mem)      memo[b * DD + f] = acc[r][c] + bm[f];
            else if (f < DD) v1[b * DD + f] = acc[r][c];
            else             v2[b * DD + (f - DD)] = acc[r][c];
        }
    }
}

// ---------------------------------------------------------------------------
// Two-pass attention read (R8 structure — 125.4us / 62.7% DRAM baseline).
// One CTA per batch, 256 threads (8 warps).
// Phase A: partial logits in registers; kbp via __ldcs (read-once,
// evict-first) so kb lines survive in L2 for phase C's re-read.
// Reduce + softmax once per batch. Phase C: weighted sum, re-reads kb.
// Only 4 __syncthreads per batch.
// ---------------------------------------------------------------------------
__global__ __launch_bounds__(256) void attn_kernel(
    const float* __restrict__ kb, const float* __restrict__ kbp,
    const float* __restrict__ memo, const float* __restrict__ v1,
    const float* __restrict__ v2, float* __restrict__ out)
{
    __shared__ float su1[DD];
    __shared__ float su2[DD];
    __shared__ float part[8 * NP];
    __shared__ float sw[NP];

    const int b = blockIdx.x;
    const int tid = threadIdx.x;
    const int w = tid >> 5, lane = tid & 31;
    const float* kbB = kb  + (size_t)b * DD * NN;
    const float* kpB = kbp + (size_t)b * DD * NN;

    // u1 = v1*mem, u2 = v2
    su1[tid]       = v1[b * DD + tid]       * memo[b * DD + tid];
    su1[tid + 256] = v1[b * DD + tid + 256] * memo[b * DD + tid + 256];
    su2[tid]       = v2[b * DD + tid];
    su2[tid + 256] = v2[b * DD + tid + 256];
    __syncthreads();

    // ---- Phase A: partial logits. warp w owns d in [w*64, w*64+64). ----
    {
        float acc[7] = {};
        const int d0 = w * 64;
#pragma unroll 2
        for (int dd = 0; dd < 64; dd += 2) {
            const int d = d0 + dd;
            const float a1 = su1[d],     a2 = su2[d];
            const float c1 = su1[d + 1], c2 = su2[d + 1];
            const float* p0 = kpB + (size_t)d * NN;
            const float* k0 = kbB + (size_t)d * NN;
#pragma unroll
            for (int j = 0; j < 6; j++) {
                const int n = lane + 32 * j;
                acc[j] += a1 * __ldcs(p0 + n)      + a2 * k0[n]
                        + c1 * __ldcs(p0 + NN + n) + c2 * k0[NN + n];
            }
            if (lane < 4) {
                const int n = 192 + lane;
                acc[6] += a1 * __ldcs(p0 + n)      + a2 * k0[n]
                        + c1 * __ldcs(p0 + NN + n) + c2 * k0[NN + n];
            }
        }
#pragma unroll
        for (int j = 0; j < 7; j++) part[w * NP + lane + 32 * j] = acc[j];
    }
    __syncthreads();

    // ---- reduce partials across warps ----
    if (tid < NP) {
        float s = 0.f;
#pragma unroll
        for (int w2 = 0; w2 < 8; w2++) s += part[w2 * NP + tid];
        sw[tid] = (tid < NN) ? s : -1e30f;
    }
    __syncthreads();

    // ---- softmax (warp 0): sw[n] = exp(l-m)/S ----
    if (w == 0) {
        float l[7];
#pragma unroll
        for (int j = 0; j < 7; j++) l[j] = sw[lane + 32 * j];
        float m = l[0];
#pragma unroll
        for (int j = 1; j < 7; j++) m = fmaxf(m, l[j]);
#pragma unroll
        for (int off = 16; off; off >>= 1)
            m = fmaxf(m, __shfl_xor_sync(0xffffffffu, m, off));
        float e[7], S = 0.f;
#pragma unroll
        for (int j = 0; j < 7; j++) { e[j] = __expf(l[j] - m); S += e[j]; }
#pragma unroll
        for (int off = 16; off; off >>= 1)
            S += __shfl_xor_sync(0xffffffffu, S, off);
        const float inv = 1.f / S;
#pragma unroll
        for (int j = 0; j < 7; j++) sw[lane + 32 * j] = e[j] * inv;
    }
    __syncthreads();

    // ---- Phase C: out[d] = sum_n sw[n]*kb[d,n]. Same warp/d mapping. ----
    {
        float swr[7];
#pragma unroll
        for (int j = 0; j < 7; j++) swr[j] = sw[lane + 32 * j];
        const int d0 = w * 64;
#pragma unroll 2
        for (int dd = 0; dd < 64; dd += 2) {
            const int d = d0 + dd;
            const float* k0 = kbB + (size_t)d * NN;
            float s0 = 0.f, s1 = 0.f;
#pragma unroll
            for (int j = 0; j < 6; j++) {
                const int n = lane + 32 * j;
                s0 += swr[j] * k0[n];
                s1 += swr[j] * k0[NN + n];
            }
            if (lane < 4) {
                s0 += swr[6] * k0[192 + lane];
                s1 += swr[6] * k0[NN + 192 + lane];
            }
#pragma unroll
            for (int off = 16; off; off >>= 1) {
                s0 += __shfl_xor_sync(0xffffffffu, s0, off);
                s1 += __shfl_xor_sync(0xffffffffu, s1, off);
            }
            if (!lane) *(float2*)(out + b * DD + d) = make_float2(s0, s1);
        }
    }
}

// ---------------------------------------------------------------------------
extern "C" void kernel_launch(void* const* d_in, const int* in_sizes, int n_in,
                              void* d_out, int out_size)
{
    const float* memory_state   = (const float*)d_in[0];  // [B, D]
    const float* knowledge_base = (const float*)d_in[1];  // [B, D, N]
    const float* ctrl_state     = (const float*)d_in[2];  // [B, D]
    const float* kb_proj        = (const float*)d_in[3];  // [B, D, N]
    const float* W_mem          = (const float*)d_in[4];  // [D, D]
    const float* b_mem          = (const float*)d_in[5];  // [D]
    const float* W_cat          = (const float*)d_in[6];  // [D, 2D]
    // d_in[7] = b_cat, d_in[9] = b_attn: softmax-invariant, dropped exactly
    const float* W_attn         = (const float*)d_in[8];  // [1, D]
    float* out = (float*)d_out;                           // [B, D]

    float* memo; cudaGetSymbolAddress((void**)&memo, g_mem);
    float* v1;   cudaGetSymbolAddress((void**)&v1,  g_v1);
    float* v2;   cudaGetSymbolAddress((void**)&v2,  g_v2);

    gemm_kernel<<<dim3(24, 16), 128>>>(memory_state, W_mem, b_mem,
                                       ctrl_state, W_attn, W_cat, memo, v1, v2,
                                       knowledge_base, kb_proj);
    attn_kernel<<<BB, 256>>>(knowledge_base, kb_proj, memo, v1, v2, out);
}

// round 14
// speedup vs baseline: 1.4784x; 1.4784x over previous
#include <cuda_runtime.h>

#define BB 512
#define DD 512
#define NN 196
#define NP 224   // n padded to 7*32

// scratch (no cudaMalloc allowed)
__device__ float g_mem[BB * DD];
__device__ float g_v1[BB * DD];
__device__ float g_v2[BB * DD];

// ---------------------------------------------------------------------------
// Fused GEMM (exact R8 config):  mem = ms @ Wm^T + bm   (f-tiles 0..7)
//                                v = (ctrl*Wattn)@Wcat  (f-tiles 8..23)
// 32(b) x 64(f) tile, 128 threads, 4x4 per thread, k-tile 16. grid 24x16=384.
// ---------------------------------------------------------------------------
__global__ __launch_bounds__(128) void gemm_kernel(
    const float* __restrict__ ms, const float* __restrict__ Wm,
    const float* __restrict__ bm, const float* __restrict__ ctrl,
    const float* __restrict__ Wattn, const float* __restrict__ Wcat,
    float* __restrict__ memo, float* __restrict__ v1, float* __restrict__ v2)
{
    __shared__ float As[16][36];
    __shared__ float Bs[16][68];
    const int t = threadIdx.x;
    const int tx = t & 15, ty = t >> 4;
    const int b0 = blockIdx.y * 32;
    const bool is_mem = (blockIdx.x < 8);
    const int f0 = is_mem ? blockIdx.x * 64 : (blockIdx.x - 8) * 64;
    const int arow = t >> 2, kq = (t & 3) << 2;
    float acc[4][4] = {};

    for (int k0 = 0; k0 < DD; k0 += 16) {
        float4 av;
        if (is_mem) {
            av = *(const float4*)(ms + (b0 + arow) * DD + k0 + kq);
        } else {
            float4 c4 = *(const float4*)(ctrl + (b0 + arow) * DD + k0 + kq);
            float4 w4 = *(const float4*)(Wattn + k0 + kq);
            av = make_float4(c4.x * w4.x, c4.y * w4.y, c4.z * w4.z, c4.w * w4.w);
        }
        As[kq + 0][arow] = av.x; As[kq + 1][arow] = av.y;
        As[kq + 2][arow] = av.z; As[kq + 3][arow] = av.w;

        if (is_mem) {  // Wm[f][k] -> transpose to Bs[k][f]
#pragma unroll
            for (int r = 0; r < 2; r++) {
                int idx = t + 128 * r;
                int fr = idx >> 2, kk = (idx & 3) << 2;
                float4 bv = *(const float4*)(Wm + (f0 + fr) * DD + k0 + kk);
                Bs[kk + 0][fr] = bv.x; Bs[kk + 1][fr] = bv.y;
                Bs[kk + 2][fr] = bv.z; Bs[kk + 3][fr] = bv.w;
            }
        } else {       // Wcat[k][f] already k-major
#pragma unroll
            for (int r = 0; r < 2; r++) {
                int idx = t + 128 * r;
                int kk = idx >> 4, fq = (idx & 15) << 2;
                *(float4*)&Bs[kk][fq] =
                    *(const float4*)(Wcat + (size_t)(k0 + kk) * (2 * DD) + f0 + fq);
            }
        }
        __syncthreads();
#pragma unroll
        for (int k = 0; k < 16; k++) {
            float4 a = *(const float4*)&As[k][ty * 4];
            float4 b = *(const float4*)&Bs[k][tx * 4];
            float aa[4] = {a.x, a.y, a.z, a.w};
            float bb[4] = {b.x, b.y, b.z, b.w};
#pragma unroll
            for (int r = 0; r < 4; r++)
#pragma unroll
                for (int c = 0; c < 4; c++) acc[r][c] += aa[r] * bb[c];
        }
        __syncthreads();
    }

#pragma unroll
    for (int r = 0; r < 4; r++) {
        int b = b0 + ty * 4 + r;
#pragma unroll
        for (int c = 0; c < 4; c++) {
            int f = f0 + tx * 4 + c;
            if (is_mem)      memo[b * DD + f] = acc[r][c] + bm[f];
            else if (f < DD) v1[b * DD + f] = acc[r][c];
            else             v2[b * DD + (f - DD)] = acc[r][c];
        }
    }
}

// ---------------------------------------------------------------------------
// Two-pass attention read — R8 structure with LDG.128 streaming.
// One CTA per batch, 256 threads (8 warps), 4 syncs per batch.
// Lane reads float4 at n=4*lane (n<128) and, for lane<17, at n=128+4*lane
// (covers n in [128,196)). Zero-fill keeps the reduce/softmax unchanged.
// ---------------------------------------------------------------------------
__global__ __launch_bounds__(256) void attn_kernel(
    const float* __restrict__ kb, const float* __restrict__ kbp,
    const float* __restrict__ memo, const float* __restrict__ v1,
    const float* __restrict__ v2, float* __restrict__ out)
{
    __shared__ float su1[DD];
    __shared__ float su2[DD];
    __shared__ __align__(16) float part[8 * NP];
    __shared__ __align__(16) float sw[NP];

    const int b = blockIdx.x;
    const int tid = threadIdx.x;
    const int w = tid >> 5, lane = tid & 31;
    const float* kbB = kb  + (size_t)b * DD * NN;
    const float* kpB = kbp + (size_t)b * DD * NN;

    // u1 = v1*mem, u2 = v2
    su1[tid]       = v1[b * DD + tid]       * memo[b * DD + tid];
    su1[tid + 256] = v1[b * DD + tid + 256] * memo[b * DD + tid + 256];
    su2[tid]       = v2[b * DD + tid];
    su2[tid + 256] = v2[b * DD + tid + 256];
    __syncthreads();

    const int na = 4 * lane;          // group-a n base (n < 128)
    const int nb = 128 + 4 * lane;    // group-b n base (lane < 17)
    const bool hasb = (lane < 17);

    // ---- Phase A: partial logits. warp w owns d in [w*64, w*64+64). ----
    {
        float4 acc_a = make_float4(0.f, 0.f, 0.f, 0.f);
        float4 acc_b = make_float4(0.f, 0.f, 0.f, 0.f);
        const int d0 = w * 64;
#pragma unroll 2
        for (int dd = 0; dd < 64; dd += 2) {
            const int d = d0 + dd;
            const float a1 = su1[d],     a2 = su2[d];
            const float c1 = su1[d + 1], c2 = su2[d + 1];
            const float* p0 = kpB + (size_t)d * NN;
            const float* k0 = kbB + (size_t)d * NN;

            float4 pa0 = *(const float4*)(p0 + na);
            float4 ka0 = *(const float4*)(k0 + na);
            float4 pa1 = *(const float4*)(p0 + NN + na);
            float4 ka1 = *(const float4*)(k0 + NN + na);
            acc_a.x += a1 * pa0.x + a2 * ka0.x + c1 * pa1.x + c2 * ka1.x;
            acc_a.y += a1 * pa0.y + a2 * ka0.y + c1 * pa1.y + c2 * ka1.y;
            acc_a.z += a1 * pa0.z + a2 * ka0.z + c1 * pa1.z + c2 * ka1.z;
            acc_a.w += a1 * pa0.w + a2 * ka0.w + c1 * pa1.w + c2 * ka1.w;

            if (hasb) {
                float4 pb0 = *(const float4*)(p0 + nb);
                float4 kb0 = *(const float4*)(k0 + nb);
                float4 pb1 = *(const float4*)(p0 + NN + nb);
                float4 kb1 = *(const float4*)(k0 + NN + nb);
                acc_b.x += a1 * pb0.x + a2 * kb0.x + c1 * pb1.x + c2 * kb1.x;
                acc_b.y += a1 * pb0.y + a2 * kb0.y + c1 * pb1.y + c2 * kb1.y;
                acc_b.z += a1 * pb0.z + a2 * kb0.z + c1 * pb1.z + c2 * kb1.z;
                acc_b.w += a1 * pb0.w + a2 * kb0.w + c1 * pb1.w + c2 * kb1.w;
            }
        }
        *(float4*)&part[w * NP + na] = acc_a;
        if (hasb)           *(float4*)&part[w * NP + nb] = acc_b;
        else if (lane < 24) *(float4*)&part[w * NP + nb] =
                                make_float4(0.f, 0.f, 0.f, 0.f);
    }
    __syncthreads();

    // ---- reduce partials across warps ----
    if (tid < NP) {
        float s = 0.f;
#pragma unroll
        for (int w2 = 0; w2 < 8; w2++) s += part[w2 * NP + tid];
        sw[tid] = (tid < NN) ? s : -1e30f;
    }
    __syncthreads();

    // ---- softmax (warp 0): sw[n] = exp(l-m)/S ----
    if (w == 0) {
        float l[7];
#pragma unroll
        for (int j = 0; j < 7; j++) l[j] = sw[lane + 32 * j];
        float m = l[0];
#pragma unroll
        for (int j = 1; j < 7; j++) m = fmaxf(m, l[j]);
#pragma unroll
        for (int off = 16; off; off >>= 1)
            m = fmaxf(m, __shfl_xor_sync(0xffffffffu, m, off));
        float e[7], S = 0.f;
#pragma unroll
        for (int j = 0; j < 7; j++) { e[j] = __expf(l[j] - m); S += e[j]; }
#pragma unroll
        for (int off = 16; off; off >>= 1)
            S += __shfl_xor_sync(0xffffffffu, S, off);
        const float inv = 1.f / S;
#pragma unroll
        for (int j = 0; j < 7; j++) sw[lane + 32 * j] = e[j] * inv;
    }
    __syncthreads();

    // ---- Phase C: out[d] = sum_n sw[n]*kb[d,n]. Same mapping, LDG.128. ----
    {
        const float4 wa = *(const float4*)&sw[na];
        const float4 wb = hasb ? *(const float4*)&sw[nb]
                               : make_float4(0.f, 0.f, 0.f, 0.f);
        const int d0 = w * 64;
#pragma unroll 2
        for (int dd = 0; dd < 64; dd += 2) {
            const int d = d0 + dd;
            const float* k0 = kbB + (size_t)d * NN;
            float s0, s1;
            {
                float4 ka0 = *(const float4*)(k0 + na);
                float4 ka1 = *(const float4*)(k0 + NN + na);
                s0 = wa.x * ka0.x + wa.y * ka0.y + wa.z * ka0.z + wa.w * ka0.w;
                s1 = wa.x * ka1.x + wa.y * ka1.y + wa.z * ka1.z + wa.w * ka1.w;
            }
            if (hasb) {
                float4 kb0 = *(const float4*)(k0 + nb);
                float4 kb1 = *(const float4*)(k0 + NN + nb);
                s0 += wb.x * kb0.x + wb.y * kb0.y + wb.z * kb0.z + wb.w * kb0.w;
                s1 += wb.x * kb1.x + wb.y * kb1.y + wb.z * kb1.z + wb.w * kb1.w;
            }
#pragma unroll
            for (int off = 16; off; off >>= 1) {
                s0 += __shfl_xor_sync(0xffffffffu, s0, off);
                s1 += __shfl_xor_sync(0xffffffffu, s1, off);
            }
            if (!lane) *(float2*)(out + b * DD + d) = make_float2(s0, s1);
        }
    }
}

// ---------------------------------------------------------------------------
extern "C" void kernel_launch(void* const* d_in, const int* in_sizes, int n_in,
                              void* d_out, int out_size)
{
    const float* memory_state   = (const float*)d_in[0];  // [B, D]
    const float* knowledge_base = (const float*)d_in[1];  // [B, D, N]
    const float* ctrl_state     = (const float*)d_in[2];  // [B, D]
    const float* kb_proj        = (const float*)d_in[3];  // [B, D, N]
    const float* W_mem          = (const float*)d_in[4];  // [D, D]
    const float* b_mem          = (const float*)d_in[5];  // [D]
    const float* W_cat          = (const float*)d_in[6];  // [D, 2D]
    // d_in[7] = b_cat, d_in[9] = b_attn: softmax-invariant, dropped exactly
    const float* W_attn         = (const float*)d_in[8];  // [1, D]
    float* out = (float*)d_out;                           // [B, D]

    float* memo; cudaGetSymbolAddress((void**)&memo, g_mem);
    float* v1;   cudaGetSymbolAddress((void**)&v1,  g_v1);
    float* v2;   cudaGetSymbolAddress((void**)&v2,  g_v2);

    gemm_kernel<<<dim3(24, 16), 128>>>(memory_state, W_mem, b_mem,
                                       ctrl_state, W_attn, W_cat, memo, v1, v2);
    attn_kernel<<<BB, 256>>>(knowledge_base, kb_proj, memo, v1, v2, out);
}